// round 12
// baseline (speedup 1.0000x reference)
#include <cuda_runtime.h>
#include <cuda_bf16.h>
#include <math.h>
#include <stdint.h>

// ---------------------------------------------------------------------------
// Problem constants
// ---------------------------------------------------------------------------
#define DIN   768
#define DOUT  768
#define NB    6                  // GRID_NUM + K
#define NAUG  7                  // silu + 6 basis
#define KDIM  (NAUG * DIN)       // 5376
#define KC    64                 // bf16 elements per K-chunk (128 bytes/row)
#define NKC   (KDIM / KC)        // 84 chunks
#define NSPLIT 3                 // split-K factor
#define NKC_SPLIT (NKC / NSPLIT) // 28 chunks per split
#define TILE_BYTES 16384         // 128 rows x 128 bytes (SW128 swizzled)
#define MAX_NTOK 8192
#define MT_MAX (MAX_NTOK / 128)  // 64 M tiles
#define NT     (DOUT / 128)      // 6 N tiles

// Pre-swizzled bf16 tile storage (hi / lo splits) + split-K partials.
__device__ __align__(1024) unsigned char g_Ahi[(size_t)MT_MAX * NKC * TILE_BYTES];
__device__ __align__(1024) unsigned char g_Alo[(size_t)MT_MAX * NKC * TILE_BYTES];
__device__ __align__(1024) unsigned char g_Whi[(size_t)NT * NKC * TILE_BYTES];
__device__ __align__(1024) unsigned char g_Wlo[(size_t)NT * NKC * TILE_BYTES];
__device__ __align__(16)   float g_part[NSPLIT][(size_t)MAX_NTOK * DOUT];

#define SWZ(o) ((o) ^ ((((uint32_t)(o)) >> 3) & 0x70u))

// ---------------------------------------------------------------------------
// PTX helpers — family-agnostic only (compiles for compute_103 target)
// ---------------------------------------------------------------------------
__device__ __forceinline__ uint32_t smem_u32(const void* p) {
    uint32_t a;
    asm("{ .reg .u64 t; cvta.to.shared.u64 t, %1; cvt.u32.u64 %0, t; }" : "=r"(a) : "l"(p));
    return a;
}

#define MBARRIER_INIT(addr, cnt) \
    asm volatile("mbarrier.init.shared.b64 [%0], %1;" :: "r"(addr), "r"(cnt) : "memory")

#define MBARRIER_EXPECT_TX(addr, bytes) \
    asm volatile("mbarrier.arrive.expect_tx.shared.b64 _, [%0], %1;" :: "r"(addr), "r"(bytes) : "memory")

#define MBARRIER_ARRIVE(addr) \
    asm volatile("mbarrier.arrive.shared.b64 _, [%0];" :: "r"(addr) : "memory")

__device__ __forceinline__ void mbar_wait_parity(uint32_t mbar, uint32_t parity) {
    uint32_t done;
    asm volatile(
        "{ .reg .pred p; mbarrier.try_wait.parity.acquire.cta.shared::cta.b64 p, [%1], %2; selp.b32 %0, 1, 0, p; }"
        : "=r"(done) : "r"(mbar), "r"(parity) : "memory");
    if (!done) {
        asm volatile(
            "{ .reg .pred P1;\n"
            "WL_%=: mbarrier.try_wait.parity.acquire.cta.shared::cta.b64 P1, [%0], %1, 0x989680;\n"
            "@P1 bra.uni WD_%=;\n"
            "bra.uni WL_%=;\n"
            "WD_%=: }\n"
            :: "r"(mbar), "r"(parity) : "memory");
    }
}

__device__ __forceinline__ void bulk_copy_g2s(uint32_t dst, const void* src,
                                              uint32_t bytes, uint32_t mbar) {
    asm volatile(
        "cp.async.bulk.shared::cluster.global.mbarrier::complete_tx::bytes [%0], [%1], %2, [%3];"
        :: "r"(dst), "l"(src), "r"(bytes), "r"(mbar) : "memory");
}

#define FENCE_PROXY_ASYNC() asm volatile("fence.proxy.async.shared::cta;" ::: "memory")

__device__ __forceinline__ void ldmatrix_x4(uint32_t& r0, uint32_t& r1,
                                            uint32_t& r2, uint32_t& r3, uint32_t addr) {
    asm volatile("ldmatrix.sync.aligned.m8n8.x4.shared.b16 {%0,%1,%2,%3}, [%4];"
                 : "=r"(r0), "=r"(r1), "=r"(r2), "=r"(r3) : "r"(addr));
}

__device__ __forceinline__ void mma_16816(float* c, const uint32_t* a,
                                          uint32_t b0, uint32_t b1) {
    asm volatile(
        "mma.sync.aligned.m16n8k16.row.col.f32.bf16.bf16.f32 "
        "{%0,%1,%2,%3}, {%4,%5,%6,%7}, {%8,%9}, {%0,%1,%2,%3};"
        : "+f"(c[0]), "+f"(c[1]), "+f"(c[2]), "+f"(c[3])
        : "r"(a[0]), "r"(a[1]), "r"(a[2]), "r"(a[3]), "r"(b0), "r"(b1));
}

// ---------------------------------------------------------------------------
// B-spline helpers (fp32, identical to reference arithmetic)
// ---------------------------------------------------------------------------
__device__ __forceinline__ float gridv(int t) {
    return (float)(t - 3) * 0.66666668653488159f - 1.0f;
}

__device__ __forceinline__ void bspline6(float xv, float* out6) {
    float b[9];
#pragma unroll
    for (int t = 0; t < 9; t++)
        b[t] = (xv >= gridv(t) && xv < gridv(t + 1)) ? 1.0f : 0.0f;
#pragma unroll
    for (int p = 1; p <= 3; p++) {
#pragma unroll
        for (int t = 0; t < 8; t++) {
            if (t < 9 - p) {
                float gl = gridv(t), glp = gridv(t + p);
                float g1 = gridv(t + 1), grp = gridv(t + p + 1);
                float left  = (xv - gl)  / (glp - gl);
                float right = (grp - xv) / (grp - g1);
                b[t] = left * b[t] + right * b[t + 1];
            }
        }
    }
#pragma unroll
    for (int j = 0; j < 6; j++) out6[j] = b[j];
}

union Pack8 {
    uint4 q;
    unsigned short s[8];
};

__device__ __forceinline__ void split_store(float v, Pack8& hi, Pack8& lo, int slot) {
    __nv_bfloat16 h = __float2bfloat16_rn(v);
    float rem = v - __bfloat162float(h);
    __nv_bfloat16 l = __float2bfloat16_rn(rem);
    hi.s[slot] = __bfloat16_as_ushort(h);
    lo.s[slot] = __bfloat16_as_ushort(l);
}

__device__ __forceinline__ void split2(float v, unsigned short& h16, unsigned short& l16) {
    __nv_bfloat16 h = __float2bfloat16_rn(v);
    float rem = v - __bfloat162float(h);
    __nv_bfloat16 l = __float2bfloat16_rn(rem);
    h16 = __bfloat16_as_ushort(h);
    l16 = __bfloat16_as_ushort(l);
}

// ---------------------------------------------------------------------------
// Kernel 1 (fused prep):
//   blocks [0, NBLK_PACK)            : pack W tiles (scale_base | scale_sp*coef)
//   blocks [NBLK_PACK, +ntok*3)      : build A tiles via smem transpose staging
// Both halves run concurrently across the chip. Low register pressure in both
// branches (build branch keeps only 1 element's state; smem does the transpose).
// ---------------------------------------------------------------------------
#define PACK_TOTAL (DOUT * (KDIM / 8))          // 516096
#define NBLK_PACK  ((PACK_TOTAL + 255) / 256)   // 2016

__global__ __launch_bounds__(256)
void prep_kernel(const float* __restrict__ x,
                 const float* __restrict__ coef,
                 const float* __restrict__ sb,
                 const float* __restrict__ ss,
                 int ntok) {
    __shared__ unsigned short s_hi[NAUG][256];   // 3.5 KB
    __shared__ unsigned short s_lo[NAUG][256];   // 3.5 KB

    if (blockIdx.x < NBLK_PACK) {
        // ---- pack W (scale_base | scale_sp*coef) ----
        int idx = blockIdx.x * 256 + threadIdx.x;
        if (idx >= PACK_TOTAL) return;
        int o  = idx / (KDIM / 8);
        int k8 = idx % (KDIM / 8);
        int j  = k8 / 96;
        int ib = (k8 % 96) * 8;

        float vals[8];
        if (j == 0) {
#pragma unroll
            for (int v = 0; v < 8; v++) vals[v] = sb[(size_t)o * DIN + ib + v];
        } else {
#pragma unroll
            for (int v = 0; v < 8; v++) {
                size_t e = (size_t)o * DIN + ib + v;
                vals[v] = ss[e] * coef[e * NB + (j - 1)];
            }
        }

        int ntile = o >> 7, r = o & 127;
        int kc = k8 >> 3;
        int cb = (k8 & 7) * 8;
        size_t tb = ((size_t)(ntile * NKC + kc)) << 14;
        uint32_t off = SWZ((uint32_t)(r * 128 + cb * 2));
        Pack8 hi, lo;
#pragma unroll
        for (int v = 0; v < 8; v++) split_store(vals[v], hi, lo, v);
        *(uint4*)(g_Whi + tb + off) = hi.q;
        *(uint4*)(g_Wlo + tb + off) = lo.q;
    } else {
        // ---- build augmented A: one element per thread, transpose via smem ----
        int bb  = blockIdx.x - NBLK_PACK;   // 0 .. ntok*3-1
        int n   = bb / 3;                   // token
        int seg = bb % 3;                   // feature segment (256 features)
        int tid = threadIdx.x;
        int i   = seg * 256 + tid;          // feature index

        float xv = x[(size_t)n * DIN + i];
        float aug0 = xv / (1.0f + expf(-xv));   // silu
        float b6[6];
        bspline6(xv, b6);

        unsigned short h16, l16;
        split2(aug0, h16, l16);
        s_hi[0][tid] = h16; s_lo[0][tid] = l16;
#pragma unroll
        for (int j = 0; j < 6; j++) {
            split2(b6[j], h16, l16);
            s_hi[j + 1][tid] = h16;
            s_lo[j + 1][tid] = l16;
        }
        __syncthreads();

        // 224 store threads: j = tid/32 (aug), g = tid%32 (8-feature group)
        if (tid < NAUG * 32) {
            int j = tid >> 5;
            int g = tid & 31;
            int f = seg * 256 + g * 8;
            int k = j * DIN + f;
            int kc = k >> 6;
            int cb = k & 63;
            int mt = n >> 7, r = n & 127;
            size_t tb = ((size_t)(mt * NKC + kc)) << 14;
            uint32_t off = SWZ((uint32_t)(r * 128 + cb * 2));
            uint4 hq = *(const uint4*)&s_hi[j][g * 8];
            uint4 lq = *(const uint4*)&s_lo[j][g * 8];
            *(uint4*)(g_Ahi + tb + off) = hq;
            *(uint4*)(g_Alo + tb + off) = lq;
        }
    }
}

// ---------------------------------------------------------------------------
// Kernel 2: mma.sync bf16x3 GEMM, split-K x3, warp-specialized.
// 288 threads: warps 0-7 compute (2Mx4N, warp tile 64x32), warp 8 = producer.
// 3-stage cp.async.bulk pipeline; consumed-mbarrier (count 8) per stage lets
// the producer refill a stage as soon as all warps finished their ldmatrix
// reads of it (overlapping refill with the MMAs of the same chunk).
// ---------------------------------------------------------------------------
#define STAGE_BYTES 65536u
#define NSTG 3

__global__ __launch_bounds__(288, 1)
void gemm_kernel(int ntok) {
    extern __shared__ __align__(16) unsigned char smem[];
    uint32_t sbase = smem_u32(smem);
    uint32_t tiles = (sbase + 96 + 1023) & ~1023u;

    const int tid  = threadIdx.x;
    const int wid  = tid >> 5;
    const int lane = tid & 31;
    const int bn = blockIdx.x;            // 0..5
    const int bm = blockIdx.y;            // 0..mtiles-1
    const int ks = blockIdx.z;            // 0..2 split-K
    const int wm = wid & 1;               // 0..1  (M)  [compute warps only]
    const int wn = wid >> 1;              // 0..3  (N)

    // full barriers: sbase + 0,16,32 ; consumed barriers: sbase + 48,64,80
    if (tid == 0) {
#pragma unroll
        for (int s = 0; s < NSTG; s++) {
            MBARRIER_INIT(sbase + 16 * s, 1);        // full (tx-based)
            MBARRIER_INIT(sbase + 48 + 16 * s, 8);   // consumed (8 compute warps)
        }
        FENCE_PROXY_ASYNC();
    }
    __syncthreads();

    const int c0 = ks * NKC_SPLIT;
    const unsigned char* Ah = g_Ahi + (((size_t)(bm * NKC + c0)) << 14);
    const unsigned char* Al = g_Alo + (((size_t)(bm * NKC + c0)) << 14);
    const unsigned char* Wh = g_Whi + (((size_t)(bn * NKC + c0)) << 14);
    const unsigned char* Wl = g_Wlo + (((size_t)(bn * NKC + c0)) << 14);

    if (wid == 8) {
        // ================= producer warp =================
        if (lane == 0) {
            for (int c = 0; c < NKC_SPLIT; c++) {
                int s = c % NSTG;
                uint32_t fb = sbase + 16 * s;
                uint32_t cons = sbase + 48 + 16 * s;
                if (c >= NSTG) {
                    int j = c / NSTG;
                    mbar_wait_parity(cons, (uint32_t)((j - 1) & 1));
                }
                uint32_t t = tiles + s * STAGE_BYTES;
                MBARRIER_EXPECT_TX(fb, STAGE_BYTES);
                bulk_copy_g2s(t,          Ah + ((size_t)c << 14), 16384, fb);
                bulk_copy_g2s(t + 16384,  Al + ((size_t)c << 14), 16384, fb);
                bulk_copy_g2s(t + 32768,  Wh + ((size_t)c << 14), 16384, fb);
                bulk_copy_g2s(t + 49152,  Wl + ((size_t)c << 14), 16384, fb);
            }
        }
        return;   // producer warp exits; no epilogue work
    }

    // ================= compute warps (0-7) =================
    const int a_row = wm * 64 + (lane & 15);
    const int a_kb  = (lane >> 4) * 16;
    const int b_row = wn * 32 + ((lane >> 4) << 3) + (lane & 7);
    const int b_kb  = ((lane >> 3) & 1) * 16;

    float acc[4][4][4];
#pragma unroll
    for (int i = 0; i < 4; i++)
#pragma unroll
        for (int j = 0; j < 4; j++)
#pragma unroll
            for (int q = 0; q < 4; q++) acc[i][j][q] = 0.0f;

    for (int c = 0; c < NKC_SPLIT; c++) {
        int s = c % NSTG;
        uint32_t fb   = sbase + 16 * s;
        uint32_t cons = sbase + 48 + 16 * s;
        mbar_wait_parity(fb, (uint32_t)((c / NSTG) & 1));

        uint32_t t  = tiles + s * STAGE_BYTES;
        uint32_t tAh = t, tAl = t + 16384, tBh = t + 32768, tBl = t + 49152;

#pragma unroll
        for (int kk = 0; kk < 4; kk++) {
            uint32_t afh[4][4], afl[4][4];
            uint32_t bfh[2][4], bfl[2][4];
#pragma unroll
            for (int mb = 0; mb < 4; mb++) {
                uint32_t off = SWZ((uint32_t)((a_row + mb * 16) * 128 + kk * 32 + a_kb));
                ldmatrix_x4(afh[mb][0], afh[mb][1], afh[mb][2], afh[mb][3], tAh + off);
                ldmatrix_x4(afl[mb][0], afl[mb][1], afl[mb][2], afl[mb][3], tAl + off);
            }
#pragma unroll
            for (int np = 0; np < 2; np++) {
                uint32_t off = SWZ((uint32_t)((b_row + np * 16) * 128 + kk * 32 + b_kb));
                ldmatrix_x4(bfh[np][0], bfh[np][1], bfh[np][2], bfh[np][3], tBh + off);
                ldmatrix_x4(bfl[np][0], bfl[np][1], bfl[np][2], bfl[np][3], tBl + off);
            }
            // After the last ldmatrix of this stage, this warp is done reading
            // the stage's smem — signal the producer (refill overlaps MMAs).
            if (kk == 3 && lane == 0) MBARRIER_ARRIVE(cons);

#pragma unroll
            for (int mb = 0; mb < 4; mb++) {
#pragma unroll
                for (int nb = 0; nb < 4; nb++) {
                    int np = nb >> 1, h = (nb & 1) * 2;
                    mma_16816(acc[mb][nb], afh[mb], bfh[np][h], bfh[np][h + 1]);
                    mma_16816(acc[mb][nb], afh[mb], bfl[np][h], bfl[np][h + 1]);
                    mma_16816(acc[mb][nb], afl[mb], bfh[np][h], bfh[np][h + 1]);
                }
            }
        }
    }

    // ---- epilogue: store fp32 partials (each warp owns its region) ----
    float* part = g_part[ks];
    const int col_base = bn * 128 + wn * 32;
    const int row_base = bm * 128 + wm * 64 + (lane >> 2);
    const int csub = (lane & 3) * 2;

#pragma unroll
    for (int mb = 0; mb < 4; mb++) {
#pragma unroll
        for (int half = 0; half < 2; half++) {
            int row = row_base + mb * 16 + half * 8;
            if (row < ntok) {
                float* op = part + (size_t)row * DOUT + col_base + csub;
#pragma unroll
                for (int nb = 0; nb < 4; nb++) {
                    float2 w;
                    w.x = acc[mb][nb][half * 2 + 0];
                    w.y = acc[mb][nb][half * 2 + 1];
                    *(float2*)(op + nb * 8) = w;
                }
            }
        }
    }
}

// ---------------------------------------------------------------------------
// Kernel 3: reduce split-K partials + bias -> out
// ---------------------------------------------------------------------------
__global__ void reduce_kernel(const float* __restrict__ bias,
                              float* __restrict__ out, int total4) {
    int idx = blockIdx.x * blockDim.x + threadIdx.x;
    if (idx >= total4) return;
    float4 p0 = ((const float4*)g_part[0])[idx];
    float4 p1 = ((const float4*)g_part[1])[idx];
    float4 p2 = ((const float4*)g_part[2])[idx];
    int col = (idx * 4) % DOUT;
    float4 b = *(const float4*)(bias + col);
    float4 w;
    w.x = p0.x + p1.x + p2.x + b.x;
    w.y = p0.y + p1.y + p2.y + b.y;
    w.z = p0.z + p1.z + p2.z + b.z;
    w.w = p0.w + p1.w + p2.w + b.w;
    ((float4*)out)[idx] = w;
}

// ---------------------------------------------------------------------------
// Launch — inputs: x, coef, scale_base, scale_sp, bias
// ---------------------------------------------------------------------------
extern "C" void kernel_launch(void* const* d_in, const int* in_sizes, int n_in,
                              void* d_out, int out_size) {
    const float* x          = (const float*)d_in[0];
    const float* coef       = (const float*)d_in[1];
    const float* scale_base = (const float*)d_in[2];
    const float* scale_sp   = (const float*)d_in[3];
    const float* bias       = (const float*)d_in[4];
    float* out = (float*)d_out;

    int ntok = in_sizes[0] / DIN;
    if (ntok > MAX_NTOK) ntok = MAX_NTOK;
    int mtiles = (ntok + 127) / 128;

    // 1) fused prep: pack W tiles + build A tiles (concurrent, low-reg)
    {
        int nblk_build = ntok * 3;   // one block per (token, 256-feature segment)
        prep_kernel<<<NBLK_PACK + nblk_build, 256>>>(x, coef, scale_base, scale_sp, ntok);
    }
    // 2) tensor-core GEMM (mma.sync bf16x3, split-K x3, warp-specialized pipe)
    {
        const int smem_req = NSTG * 65536 + 2048;
        cudaFuncSetAttribute(gemm_kernel, cudaFuncAttributeMaxDynamicSharedMemorySize, smem_req);
        dim3 grid(NT, mtiles, NSPLIT);
        gemm_kernel<<<grid, 288, smem_req>>>(ntok);
    }
    // 3) reduce partials + bias
    {
        int total4 = ntok * DOUT / 4;
        reduce_kernel<<<(total4 + 255) / 256, 256>>>(bias, out, total4);
    }
}

// round 13
// speedup vs baseline: 1.1055x; 1.1055x over previous
#include <cuda_runtime.h>
#include <cuda_bf16.h>
#include <math.h>
#include <stdint.h>

// ---------------------------------------------------------------------------
// Problem constants
// ---------------------------------------------------------------------------
#define DIN   768
#define DOUT  768
#define NB    6                  // GRID_NUM + K
#define NAUG  7                  // silu + 6 basis
#define KDIM  (NAUG * DIN)       // 5376
#define KC    64                 // bf16 elements per K-chunk (128 bytes/row)
#define NKC   (KDIM / KC)        // 84 chunks
#define NSPLIT 3                 // split-K factor
#define NKC_SPLIT (NKC / NSPLIT) // 28 chunks per split
#define TILE_BYTES 16384         // 128 rows x 128 bytes (SW128 swizzled)
#define MAX_NTOK 8192
#define MT_MAX (MAX_NTOK / 128)  // 64 M tiles
#define NT     (DOUT / 128)      // 6 N tiles

// Pre-swizzled bf16 tile storage (hi / lo splits) + split-K partials.
__device__ __align__(1024) unsigned char g_Ahi[(size_t)MT_MAX * NKC * TILE_BYTES];
__device__ __align__(1024) unsigned char g_Alo[(size_t)MT_MAX * NKC * TILE_BYTES];
__device__ __align__(1024) unsigned char g_Whi[(size_t)NT * NKC * TILE_BYTES];
__device__ __align__(1024) unsigned char g_Wlo[(size_t)NT * NKC * TILE_BYTES];
__device__ __align__(16)   float g_part[NSPLIT][(size_t)MAX_NTOK * DOUT];

#define SWZ(o) ((o) ^ ((((uint32_t)(o)) >> 3) & 0x70u))

// ---------------------------------------------------------------------------
// PTX helpers — family-agnostic only (compiles for compute_103 target)
// ---------------------------------------------------------------------------
__device__ __forceinline__ uint32_t smem_u32(const void* p) {
    uint32_t a;
    asm("{ .reg .u64 t; cvta.to.shared.u64 t, %1; cvt.u32.u64 %0, t; }" : "=r"(a) : "l"(p));
    return a;
}

#define MBARRIER_INIT(addr, cnt) \
    asm volatile("mbarrier.init.shared.b64 [%0], %1;" :: "r"(addr), "r"(cnt) : "memory")

#define MBARRIER_EXPECT_TX(addr, bytes) \
    asm volatile("mbarrier.arrive.expect_tx.shared.b64 _, [%0], %1;" :: "r"(addr), "r"(bytes) : "memory")

#define MBARRIER_ARRIVE(addr) \
    asm volatile("mbarrier.arrive.shared.b64 _, [%0];" :: "r"(addr) : "memory")

__device__ __forceinline__ void mbar_wait_parity(uint32_t mbar, uint32_t parity) {
    uint32_t done;
    asm volatile(
        "{ .reg .pred p; mbarrier.try_wait.parity.acquire.cta.shared::cta.b64 p, [%1], %2; selp.b32 %0, 1, 0, p; }"
        : "=r"(done) : "r"(mbar), "r"(parity) : "memory");
    if (!done) {
        asm volatile(
            "{ .reg .pred P1;\n"
            "WL_%=: mbarrier.try_wait.parity.acquire.cta.shared::cta.b64 P1, [%0], %1, 0x989680;\n"
            "@P1 bra.uni WD_%=;\n"
            "bra.uni WL_%=;\n"
            "WD_%=: }\n"
            :: "r"(mbar), "r"(parity) : "memory");
    }
}

__device__ __forceinline__ void bulk_copy_g2s(uint32_t dst, const void* src,
                                              uint32_t bytes, uint32_t mbar) {
    asm volatile(
        "cp.async.bulk.shared::cluster.global.mbarrier::complete_tx::bytes [%0], [%1], %2, [%3];"
        :: "r"(dst), "l"(src), "r"(bytes), "r"(mbar) : "memory");
}

#define FENCE_PROXY_ASYNC() asm volatile("fence.proxy.async.shared::cta;" ::: "memory")

__device__ __forceinline__ void ldmatrix_x4(uint32_t& r0, uint32_t& r1,
                                            uint32_t& r2, uint32_t& r3, uint32_t addr) {
    asm volatile("ldmatrix.sync.aligned.m8n8.x4.shared.b16 {%0,%1,%2,%3}, [%4];"
                 : "=r"(r0), "=r"(r1), "=r"(r2), "=r"(r3) : "r"(addr));
}

__device__ __forceinline__ void mma_16816(float* c, const uint32_t* a,
                                          uint32_t b0, uint32_t b1) {
    asm volatile(
        "mma.sync.aligned.m16n8k16.row.col.f32.bf16.bf16.f32 "
        "{%0,%1,%2,%3}, {%4,%5,%6,%7}, {%8,%9}, {%0,%1,%2,%3};"
        : "+f"(c[0]), "+f"(c[1]), "+f"(c[2]), "+f"(c[3])
        : "r"(a[0]), "r"(a[1]), "r"(a[2]), "r"(a[3]), "r"(b0), "r"(b1));
}

// ---------------------------------------------------------------------------
// B-spline helpers. Grid points identical to reference fp32 arithmetic.
// Divisions replaced by multiply-with-compile-time-constant reciprocals
// (denominators are constants; 1.0f/const folds at compile time; ~1ulp delta).
// ---------------------------------------------------------------------------
__device__ __forceinline__ float gridv(int t) {
    return (float)(t - 3) * 0.66666668653488159f - 1.0f;
}

__device__ __forceinline__ void bspline6(float xv, float* out6) {
    float b[9];
#pragma unroll
    for (int t = 0; t < 9; t++)
        b[t] = (xv >= gridv(t) && xv < gridv(t + 1)) ? 1.0f : 0.0f;
#pragma unroll
    for (int p = 1; p <= 3; p++) {
#pragma unroll
        for (int t = 0; t < 8; t++) {
            if (t < 9 - p) {
                const float gl  = gridv(t);
                const float glp = gridv(t + p);
                const float g1  = gridv(t + 1);
                const float grp = gridv(t + p + 1);
                const float invL = 1.0f / (glp - gl);   // compile-time constant
                const float invR = 1.0f / (grp - g1);   // compile-time constant
                float left  = (xv - gl)  * invL;
                float right = (grp - xv) * invR;
                b[t] = left * b[t] + right * b[t + 1];
            }
        }
    }
#pragma unroll
    for (int j = 0; j < 6; j++) out6[j] = b[j];
}

union Pack8 {
    uint4 q;
    unsigned short s[8];
};

__device__ __forceinline__ void split_store(float v, Pack8& hi, Pack8& lo, int slot) {
    __nv_bfloat16 h = __float2bfloat16_rn(v);
    float rem = v - __bfloat162float(h);
    __nv_bfloat16 l = __float2bfloat16_rn(rem);
    hi.s[slot] = __bfloat16_as_ushort(h);
    lo.s[slot] = __bfloat16_as_ushort(l);
}

__device__ __forceinline__ void split2(float v, unsigned short& h16, unsigned short& l16) {
    __nv_bfloat16 h = __float2bfloat16_rn(v);
    float rem = v - __bfloat162float(h);
    __nv_bfloat16 l = __float2bfloat16_rn(rem);
    h16 = __bfloat16_as_ushort(h);
    l16 = __bfloat16_as_ushort(l);
}

// ---------------------------------------------------------------------------
// Kernel 1 (fused prep):
//   blocks [0, NBLK_PACK)            : pack W tiles (scale_base | scale_sp*coef)
//   blocks [NBLK_PACK, +ntok*3)      : build A tiles via smem transpose staging
// ---------------------------------------------------------------------------
#define PACK_TOTAL (DOUT * (KDIM / 8))          // 516096
#define NBLK_PACK  ((PACK_TOTAL + 255) / 256)   // 2016

__global__ __launch_bounds__(256)
void prep_kernel(const float* __restrict__ x,
                 const float* __restrict__ coef,
                 const float* __restrict__ sb,
                 const float* __restrict__ ss,
                 int ntok) {
    __shared__ unsigned short s_hi[NAUG][256];   // 3.5 KB
    __shared__ unsigned short s_lo[NAUG][256];   // 3.5 KB

    if (blockIdx.x < NBLK_PACK) {
        // ---- pack W (scale_base | scale_sp*coef) ----
        int idx = blockIdx.x * 256 + threadIdx.x;
        if (idx >= PACK_TOTAL) return;
        int o  = idx / (KDIM / 8);
        int k8 = idx % (KDIM / 8);
        int j  = k8 / 96;
        int ib = (k8 % 96) * 8;

        float vals[8];
        if (j == 0) {
#pragma unroll
            for (int v = 0; v < 8; v++) vals[v] = sb[(size_t)o * DIN + ib + v];
        } else {
#pragma unroll
            for (int v = 0; v < 8; v++) {
                size_t e = (size_t)o * DIN + ib + v;
                vals[v] = ss[e] * coef[e * NB + (j - 1)];
            }
        }

        int ntile = o >> 7, r = o & 127;
        int kc = k8 >> 3;
        int cb = (k8 & 7) * 8;
        size_t tb = ((size_t)(ntile * NKC + kc)) << 14;
        uint32_t off = SWZ((uint32_t)(r * 128 + cb * 2));
        Pack8 hi, lo;
#pragma unroll
        for (int v = 0; v < 8; v++) split_store(vals[v], hi, lo, v);
        *(uint4*)(g_Whi + tb + off) = hi.q;
        *(uint4*)(g_Wlo + tb + off) = lo.q;
    } else {
        // ---- build augmented A: one element per thread, transpose via smem ----
        int bb  = blockIdx.x - NBLK_PACK;   // 0 .. ntok*3-1
        int n   = bb / 3;                   // token
        int seg = bb % 3;                   // feature segment (256 features)
        int tid = threadIdx.x;
        int i   = seg * 256 + tid;          // feature index

        float xv = x[(size_t)n * DIN + i];
        float aug0 = xv / (1.0f + __expf(-xv));   // silu (fast exp; ~1e-7 rel)
        float b6[6];
        bspline6(xv, b6);

        unsigned short h16, l16;
        split2(aug0, h16, l16);
        s_hi[0][tid] = h16; s_lo[0][tid] = l16;
#pragma unroll
        for (int j = 0; j < 6; j++) {
            split2(b6[j], h16, l16);
            s_hi[j + 1][tid] = h16;
            s_lo[j + 1][tid] = l16;
        }
        __syncthreads();

        // 224 store threads: j = tid/32 (aug), g = tid%32 (8-feature group)
        if (tid < NAUG * 32) {
            int j = tid >> 5;
            int g = tid & 31;
            int f = seg * 256 + g * 8;
            int k = j * DIN + f;
            int kc = k >> 6;
            int cb = k & 63;
            int mt = n >> 7, r = n & 127;
            size_t tb = ((size_t)(mt * NKC + kc)) << 14;
            uint32_t off = SWZ((uint32_t)(r * 128 + cb * 2));
            uint4 hq = *(const uint4*)&s_hi[j][g * 8];
            uint4 lq = *(const uint4*)&s_lo[j][g * 8];
            *(uint4*)(g_Ahi + tb + off) = hq;
            *(uint4*)(g_Alo + tb + off) = lq;
        }
    }
}

// ---------------------------------------------------------------------------
// Kernel 2: mma.sync bf16x3 GEMM, split-K x3, warp-specialized.
// 288 threads: warps 0-7 compute (2Mx4N, warp tile 64x32), warp 8 = producer.
// 3-stage cp.async.bulk pipeline; consumed-mbarrier (count 8) per stage lets
// the producer refill a stage as soon as all warps finished their ldmatrix
// reads of it (overlapping refill with the MMAs of the same chunk).
// ---------------------------------------------------------------------------
#define STAGE_BYTES 65536u
#define NSTG 3

__global__ __launch_bounds__(288, 1)
void gemm_kernel(int ntok) {
    extern __shared__ __align__(16) unsigned char smem[];
    uint32_t sbase = smem_u32(smem);
    uint32_t tiles = (sbase + 96 + 1023) & ~1023u;

    const int tid  = threadIdx.x;
    const int wid  = tid >> 5;
    const int lane = tid & 31;
    const int bn = blockIdx.x;            // 0..5
    const int bm = blockIdx.y;            // 0..mtiles-1
    const int ks = blockIdx.z;            // 0..2 split-K
    const int wm = wid & 1;               // 0..1  (M)  [compute warps only]
    const int wn = wid >> 1;              // 0..3  (N)

    // full barriers: sbase + 0,16,32 ; consumed barriers: sbase + 48,64,80
    if (tid == 0) {
#pragma unroll
        for (int s = 0; s < NSTG; s++) {
            MBARRIER_INIT(sbase + 16 * s, 1);        // full (tx-based)
            MBARRIER_INIT(sbase + 48 + 16 * s, 8);   // consumed (8 compute warps)
        }
        FENCE_PROXY_ASYNC();
    }
    __syncthreads();

    const int c0 = ks * NKC_SPLIT;
    const unsigned char* Ah = g_Ahi + (((size_t)(bm * NKC + c0)) << 14);
    const unsigned char* Al = g_Alo + (((size_t)(bm * NKC + c0)) << 14);
    const unsigned char* Wh = g_Whi + (((size_t)(bn * NKC + c0)) << 14);
    const unsigned char* Wl = g_Wlo + (((size_t)(bn * NKC + c0)) << 14);

    if (wid == 8) {
        // ================= producer warp =================
        if (lane == 0) {
            for (int c = 0; c < NKC_SPLIT; c++) {
                int s = c % NSTG;
                uint32_t fb = sbase + 16 * s;
                uint32_t cons = sbase + 48 + 16 * s;
                if (c >= NSTG) {
                    int j = c / NSTG;
                    mbar_wait_parity(cons, (uint32_t)((j - 1) & 1));
                }
                uint32_t t = tiles + s * STAGE_BYTES;
                MBARRIER_EXPECT_TX(fb, STAGE_BYTES);
                bulk_copy_g2s(t,          Ah + ((size_t)c << 14), 16384, fb);
                bulk_copy_g2s(t + 16384,  Al + ((size_t)c << 14), 16384, fb);
                bulk_copy_g2s(t + 32768,  Wh + ((size_t)c << 14), 16384, fb);
                bulk_copy_g2s(t + 49152,  Wl + ((size_t)c << 14), 16384, fb);
            }
        }
        return;   // producer warp exits; no epilogue work
    }

    // ================= compute warps (0-7) =================
    const int a_row = wm * 64 + (lane & 15);
    const int a_kb  = (lane >> 4) * 16;
    const int b_row = wn * 32 + ((lane >> 4) << 3) + (lane & 7);
    const int b_kb  = ((lane >> 3) & 1) * 16;

    float acc[4][4][4];
#pragma unroll
    for (int i = 0; i < 4; i++)
#pragma unroll
        for (int j = 0; j < 4; j++)
#pragma unroll
            for (int q = 0; q < 4; q++) acc[i][j][q] = 0.0f;

    for (int c = 0; c < NKC_SPLIT; c++) {
        int s = c % NSTG;
        uint32_t fb   = sbase + 16 * s;
        uint32_t cons = sbase + 48 + 16 * s;
        mbar_wait_parity(fb, (uint32_t)((c / NSTG) & 1));

        uint32_t t  = tiles + s * STAGE_BYTES;
        uint32_t tAh = t, tAl = t + 16384, tBh = t + 32768, tBl = t + 49152;

#pragma unroll
        for (int kk = 0; kk < 4; kk++) {
            uint32_t afh[4][4], afl[4][4];
            uint32_t bfh[2][4], bfl[2][4];
#pragma unroll
            for (int mb = 0; mb < 4; mb++) {
                uint32_t off = SWZ((uint32_t)((a_row + mb * 16) * 128 + kk * 32 + a_kb));
                ldmatrix_x4(afh[mb][0], afh[mb][1], afh[mb][2], afh[mb][3], tAh + off);
                ldmatrix_x4(afl[mb][0], afl[mb][1], afl[mb][2], afl[mb][3], tAl + off);
            }
#pragma unroll
            for (int np = 0; np < 2; np++) {
                uint32_t off = SWZ((uint32_t)((b_row + np * 16) * 128 + kk * 32 + b_kb));
                ldmatrix_x4(bfh[np][0], bfh[np][1], bfh[np][2], bfh[np][3], tBh + off);
                ldmatrix_x4(bfl[np][0], bfl[np][1], bfl[np][2], bfl[np][3], tBl + off);
            }
            // After the last ldmatrix of this stage, this warp is done reading
            // the stage's smem — signal the producer (refill overlaps MMAs).
            if (kk == 3 && lane == 0) MBARRIER_ARRIVE(cons);

#pragma unroll
            for (int mb = 0; mb < 4; mb++) {
#pragma unroll
                for (int nb = 0; nb < 4; nb++) {
                    int np = nb >> 1, h = (nb & 1) * 2;
                    mma_16816(acc[mb][nb], afh[mb], bfh[np][h], bfh[np][h + 1]);
                    mma_16816(acc[mb][nb], afh[mb], bfl[np][h], bfl[np][h + 1]);
                    mma_16816(acc[mb][nb], afl[mb], bfh[np][h], bfh[np][h + 1]);
                }
            }
        }
    }

    // ---- epilogue: store fp32 partials (each warp owns its region) ----
    float* part = g_part[ks];
    const int col_base = bn * 128 + wn * 32;
    const int row_base = bm * 128 + wm * 64 + (lane >> 2);
    const int csub = (lane & 3) * 2;

#pragma unroll
    for (int mb = 0; mb < 4; mb++) {
#pragma unroll
        for (int half = 0; half < 2; half++) {
            int row = row_base + mb * 16 + half * 8;
            if (row < ntok) {
                float* op = part + (size_t)row * DOUT + col_base + csub;
#pragma unroll
                for (int nb = 0; nb < 4; nb++) {
                    float2 w;
                    w.x = acc[mb][nb][half * 2 + 0];
                    w.y = acc[mb][nb][half * 2 + 1];
                    *(float2*)(op + nb * 8) = w;
                }
            }
        }
    }
}

// ---------------------------------------------------------------------------
// Kernel 3: reduce split-K partials + bias -> out
// ---------------------------------------------------------------------------
__global__ void reduce_kernel(const float* __restrict__ bias,
                              float* __restrict__ out, int total4) {
    int idx = blockIdx.x * blockDim.x + threadIdx.x;
    if (idx >= total4) return;
    float4 p0 = ((const float4*)g_part[0])[idx];
    float4 p1 = ((const float4*)g_part[1])[idx];
    float4 p2 = ((const float4*)g_part[2])[idx];
    int col = (idx * 4) % DOUT;
    float4 b = *(const float4*)(bias + col);
    float4 w;
    w.x = p0.x + p1.x + p2.x + b.x;
    w.y = p0.y + p1.y + p2.y + b.y;
    w.z = p0.z + p1.z + p2.z + b.z;
    w.w = p0.w + p1.w + p2.w + b.w;
    ((float4*)out)[idx] = w;
}

// ---------------------------------------------------------------------------
// Launch — inputs: x, coef, scale_base, scale_sp, bias
// ---------------------------------------------------------------------------
extern "C" void kernel_launch(void* const* d_in, const int* in_sizes, int n_in,
                              void* d_out, int out_size) {
    const float* x          = (const float*)d_in[0];
    const float* coef       = (const float*)d_in[1];
    const float* scale_base = (const float*)d_in[2];
    const float* scale_sp   = (const float*)d_in[3];
    const float* bias       = (const float*)d_in[4];
    float* out = (float*)d_out;

    int ntok = in_sizes[0] / DIN;
    if (ntok > MAX_NTOK) ntok = MAX_NTOK;
    int mtiles = (ntok + 127) / 128;

    // 1) fused prep: pack W tiles + build A tiles (concurrent, low-reg, div-free)
    {
        int nblk_build = ntok * 3;   // one block per (token, 256-feature segment)
        prep_kernel<<<NBLK_PACK + nblk_build, 256>>>(x, coef, scale_base, scale_sp, ntok);
    }
    // 2) tensor-core GEMM (mma.sync bf16x3, split-K x3, warp-specialized pipe)
    {
        const int smem_req = NSTG * 65536 + 2048;
        cudaFuncSetAttribute(gemm_kernel, cudaFuncAttributeMaxDynamicSharedMemorySize, smem_req);
        dim3 grid(NT, mtiles, NSPLIT);
        gemm_kernel<<<grid, 288, smem_req>>>(ntok);
    }
    // 3) reduce partials + bias
    {
        int total4 = ntok * DOUT / 4;
        reduce_kernel<<<(total4 + 255) / 256, 256>>>(bias, out, total4);
    }
}

// round 14
// speedup vs baseline: 1.1082x; 1.0025x over previous
#include <cuda_runtime.h>
#include <cuda_bf16.h>
#include <math.h>
#include <stdint.h>

// ---------------------------------------------------------------------------
// Problem constants
// ---------------------------------------------------------------------------
#define DIN   768
#define DOUT  768
#define NB    6                  // GRID_NUM + K
#define NAUG  7                  // silu + 6 basis
#define KDIM  (NAUG * DIN)       // 5376
#define KC    64                 // bf16 elements per K-chunk (128 bytes/row)
#define NKC   (KDIM / KC)        // 84 chunks
#define NSPLIT 3                 // split-K factor
#define NKC_SPLIT (NKC / NSPLIT) // 28 chunks per split
#define TILE_BYTES 16384         // 128 rows x 128 bytes (SW128 swizzled)
#define MAX_NTOK 8192
#define MT_MAX (MAX_NTOK / 128)  // 64 M tiles
#define NT     (DOUT / 128)      // 6 N tiles

// Pre-swizzled bf16 tile storage (hi / lo splits) + split-K partials.
__device__ __align__(1024) unsigned char g_Ahi[(size_t)MT_MAX * NKC * TILE_BYTES];
__device__ __align__(1024) unsigned char g_Alo[(size_t)MT_MAX * NKC * TILE_BYTES];
__device__ __align__(1024) unsigned char g_Whi[(size_t)NT * NKC * TILE_BYTES];
__device__ __align__(1024) unsigned char g_Wlo[(size_t)NT * NKC * TILE_BYTES];
__device__ __align__(16)   float g_part[NSPLIT][(size_t)MAX_NTOK * DOUT];

#define SWZ(o) ((o) ^ ((((uint32_t)(o)) >> 3) & 0x70u))

// ---------------------------------------------------------------------------
// PTX helpers — family-agnostic only (compiles for compute_103 target)
// ---------------------------------------------------------------------------
__device__ __forceinline__ uint32_t smem_u32(const void* p) {
    uint32_t a;
    asm("{ .reg .u64 t; cvta.to.shared.u64 t, %1; cvt.u32.u64 %0, t; }" : "=r"(a) : "l"(p));
    return a;
}

#define MBARRIER_INIT(addr, cnt) \
    asm volatile("mbarrier.init.shared.b64 [%0], %1;" :: "r"(addr), "r"(cnt) : "memory")

#define MBARRIER_EXPECT_TX(addr, bytes) \
    asm volatile("mbarrier.arrive.expect_tx.shared.b64 _, [%0], %1;" :: "r"(addr), "r"(bytes) : "memory")

#define MBARRIER_ARRIVE(addr) \
    asm volatile("mbarrier.arrive.shared.b64 _, [%0];" :: "r"(addr) : "memory")

__device__ __forceinline__ void mbar_wait_parity(uint32_t mbar, uint32_t parity) {
    uint32_t done;
    asm volatile(
        "{ .reg .pred p; mbarrier.try_wait.parity.acquire.cta.shared::cta.b64 p, [%1], %2; selp.b32 %0, 1, 0, p; }"
        : "=r"(done) : "r"(mbar), "r"(parity) : "memory");
    if (!done) {
        asm volatile(
            "{ .reg .pred P1;\n"
            "WL_%=: mbarrier.try_wait.parity.acquire.cta.shared::cta.b64 P1, [%0], %1, 0x989680;\n"
            "@P1 bra.uni WD_%=;\n"
            "bra.uni WL_%=;\n"
            "WD_%=: }\n"
            :: "r"(mbar), "r"(parity) : "memory");
    }
}

__device__ __forceinline__ void bulk_copy_g2s(uint32_t dst, const void* src,
                                              uint32_t bytes, uint32_t mbar) {
    asm volatile(
        "cp.async.bulk.shared::cluster.global.mbarrier::complete_tx::bytes [%0], [%1], %2, [%3];"
        :: "r"(dst), "l"(src), "r"(bytes), "r"(mbar) : "memory");
}

#define FENCE_PROXY_ASYNC() asm volatile("fence.proxy.async.shared::cta;" ::: "memory")

__device__ __forceinline__ void ldmatrix_x4(uint32_t& r0, uint32_t& r1,
                                            uint32_t& r2, uint32_t& r3, uint32_t addr) {
    asm volatile("ldmatrix.sync.aligned.m8n8.x4.shared.b16 {%0,%1,%2,%3}, [%4];"
                 : "=r"(r0), "=r"(r1), "=r"(r2), "=r"(r3) : "r"(addr));
}

__device__ __forceinline__ void mma_16816(float* c, const uint32_t* a,
                                          uint32_t b0, uint32_t b1) {
    asm volatile(
        "mma.sync.aligned.m16n8k16.row.col.f32.bf16.bf16.f32 "
        "{%0,%1,%2,%3}, {%4,%5,%6,%7}, {%8,%9}, {%0,%1,%2,%3};"
        : "+f"(c[0]), "+f"(c[1]), "+f"(c[2]), "+f"(c[3])
        : "r"(a[0]), "r"(a[1]), "r"(a[2]), "r"(a[3]), "r"(b0), "r"(b1));
}

// ---------------------------------------------------------------------------
// B-spline helpers. Grid points identical to reference fp32 arithmetic.
// Divisions replaced by multiply-with-compile-time-constant reciprocals
// (denominators are constants; 1.0f/const folds at compile time; ~1ulp delta).
// ---------------------------------------------------------------------------
__device__ __forceinline__ float gridv(int t) {
    return (float)(t - 3) * 0.66666668653488159f - 1.0f;
}

__device__ __forceinline__ void bspline6(float xv, float* out6) {
    float b[9];
#pragma unroll
    for (int t = 0; t < 9; t++)
        b[t] = (xv >= gridv(t) && xv < gridv(t + 1)) ? 1.0f : 0.0f;
#pragma unroll
    for (int p = 1; p <= 3; p++) {
#pragma unroll
        for (int t = 0; t < 8; t++) {
            if (t < 9 - p) {
                const float gl  = gridv(t);
                const float glp = gridv(t + p);
                const float g1  = gridv(t + 1);
                const float grp = gridv(t + p + 1);
                const float invL = 1.0f / (glp - gl);   // compile-time constant
                const float invR = 1.0f / (grp - g1);   // compile-time constant
                float left  = (xv - gl)  * invL;
                float right = (grp - xv) * invR;
                b[t] = left * b[t] + right * b[t + 1];
            }
        }
    }
#pragma unroll
    for (int j = 0; j < 6; j++) out6[j] = b[j];
}

union Pack8 {
    uint4 q;
    unsigned short s[8];
};

__device__ __forceinline__ void split_store(float v, Pack8& hi, Pack8& lo, int slot) {
    __nv_bfloat16 h = __float2bfloat16_rn(v);
    float rem = v - __bfloat162float(h);
    __nv_bfloat16 l = __float2bfloat16_rn(rem);
    hi.s[slot] = __bfloat16_as_ushort(h);
    lo.s[slot] = __bfloat16_as_ushort(l);
}

__device__ __forceinline__ void split2(float v, unsigned short& h16, unsigned short& l16) {
    __nv_bfloat16 h = __float2bfloat16_rn(v);
    float rem = v - __bfloat162float(h);
    __nv_bfloat16 l = __float2bfloat16_rn(rem);
    h16 = __bfloat16_as_ushort(h);
    l16 = __bfloat16_as_ushort(l);
}

// ---------------------------------------------------------------------------
// Kernel 1 (fused prep):
//   blocks [0, NBLK_PACK)            : pack W tiles (scale_base | scale_sp*coef)
//   blocks [NBLK_PACK, +ntok*3)      : build A tiles via smem transpose staging
// ---------------------------------------------------------------------------
#define PACK_TOTAL (DOUT * (KDIM / 8))          // 516096
#define NBLK_PACK  ((PACK_TOTAL + 255) / 256)   // 2016

__global__ __launch_bounds__(256)
void prep_kernel(const float* __restrict__ x,
                 const float* __restrict__ coef,
                 const float* __restrict__ sb,
                 const float* __restrict__ ss,
                 int ntok) {
    __shared__ unsigned short s_hi[NAUG][256];   // 3.5 KB
    __shared__ unsigned short s_lo[NAUG][256];   // 3.5 KB

    if (blockIdx.x < NBLK_PACK) {
        // ---- pack W (scale_base | scale_sp*coef) ----
        int idx = blockIdx.x * 256 + threadIdx.x;
        if (idx >= PACK_TOTAL) return;
        int o  = idx / (KDIM / 8);
        int k8 = idx % (KDIM / 8);
        int j  = k8 / 96;
        int ib = (k8 % 96) * 8;

        float vals[8];
        if (j == 0) {
#pragma unroll
            for (int v = 0; v < 8; v++) vals[v] = sb[(size_t)o * DIN + ib + v];
        } else {
#pragma unroll
            for (int v = 0; v < 8; v++) {
                size_t e = (size_t)o * DIN + ib + v;
                vals[v] = ss[e] * coef[e * NB + (j - 1)];
            }
        }

        int ntile = o >> 7, r = o & 127;
        int kc = k8 >> 3;
        int cb = (k8 & 7) * 8;
        size_t tb = ((size_t)(ntile * NKC + kc)) << 14;
        uint32_t off = SWZ((uint32_t)(r * 128 + cb * 2));
        Pack8 hi, lo;
#pragma unroll
        for (int v = 0; v < 8; v++) split_store(vals[v], hi, lo, v);
        *(uint4*)(g_Whi + tb + off) = hi.q;
        *(uint4*)(g_Wlo + tb + off) = lo.q;
    } else {
        // ---- build augmented A: one element per thread, transpose via smem ----
        int bb  = blockIdx.x - NBLK_PACK;   // 0 .. ntok*3-1
        int n   = bb / 3;                   // token
        int seg = bb % 3;                   // feature segment (256 features)
        int tid = threadIdx.x;
        int i   = seg * 256 + tid;          // feature index

        float xv = x[(size_t)n * DIN + i];
        float aug0 = xv / (1.0f + __expf(-xv));   // silu (fast exp; ~1e-7 rel)
        float b6[6];
        bspline6(xv, b6);

        unsigned short h16, l16;
        split2(aug0, h16, l16);
        s_hi[0][tid] = h16; s_lo[0][tid] = l16;
#pragma unroll
        for (int j = 0; j < 6; j++) {
            split2(b6[j], h16, l16);
            s_hi[j + 1][tid] = h16;
            s_lo[j + 1][tid] = l16;
        }
        __syncthreads();

        // 224 store threads: j = tid/32 (aug), g = tid%32 (8-feature group)
        if (tid < NAUG * 32) {
            int j = tid >> 5;
            int g = tid & 31;
            int f = seg * 256 + g * 8;
            int k = j * DIN + f;
            int kc = k >> 6;
            int cb = k & 63;
            int mt = n >> 7, r = n & 127;
            size_t tb = ((size_t)(mt * NKC + kc)) << 14;
            uint32_t off = SWZ((uint32_t)(r * 128 + cb * 2));
            uint4 hq = *(const uint4*)&s_hi[j][g * 8];
            uint4 lq = *(const uint4*)&s_lo[j][g * 8];
            *(uint4*)(g_Ahi + tb + off) = hq;
            *(uint4*)(g_Alo + tb + off) = lq;
        }
    }
}

// ---------------------------------------------------------------------------
// Kernel 2: mma.sync bf16x3 GEMM, split-K x3, warp-specialized.
// 288 threads: warps 0-7 compute (2Mx4N, warp tile 64x32), warp 8 = producer.
// 3-stage cp.async.bulk pipeline; consumed-mbarrier (count 8) per stage lets
// the producer refill a stage as soon as all warps finished their ldmatrix
// reads of it (overlapping refill with the MMAs of the same chunk).
// ---------------------------------------------------------------------------
#define STAGE_BYTES 65536u
#define NSTG 3

__global__ __launch_bounds__(288, 1)
void gemm_kernel(int ntok) {
    extern __shared__ __align__(16) unsigned char smem[];
    uint32_t sbase = smem_u32(smem);
    uint32_t tiles = (sbase + 96 + 1023) & ~1023u;

    const int tid  = threadIdx.x;
    const int wid  = tid >> 5;
    const int lane = tid & 31;
    const int bn = blockIdx.x;            // 0..5
    const int bm = blockIdx.y;            // 0..mtiles-1
    const int ks = blockIdx.z;            // 0..2 split-K
    const int wm = wid & 1;               // 0..1  (M)  [compute warps only]
    const int wn = wid >> 1;              // 0..3  (N)

    // full barriers: sbase + 0,16,32 ; consumed barriers: sbase + 48,64,80
    if (tid == 0) {
#pragma unroll
        for (int s = 0; s < NSTG; s++) {
            MBARRIER_INIT(sbase + 16 * s, 1);        // full (tx-based)
            MBARRIER_INIT(sbase + 48 + 16 * s, 8);   // consumed (8 compute warps)
        }
        FENCE_PROXY_ASYNC();
    }
    __syncthreads();

    const int c0 = ks * NKC_SPLIT;
    const unsigned char* Ah = g_Ahi + (((size_t)(bm * NKC + c0)) << 14);
    const unsigned char* Al = g_Alo + (((size_t)(bm * NKC + c0)) << 14);
    const unsigned char* Wh = g_Whi + (((size_t)(bn * NKC + c0)) << 14);
    const unsigned char* Wl = g_Wlo + (((size_t)(bn * NKC + c0)) << 14);

    if (wid == 8) {
        // ================= producer warp =================
        if (lane == 0) {
            for (int c = 0; c < NKC_SPLIT; c++) {
                int s = c % NSTG;
                uint32_t fb = sbase + 16 * s;
                uint32_t cons = sbase + 48 + 16 * s;
                if (c >= NSTG) {
                    int j = c / NSTG;
                    mbar_wait_parity(cons, (uint32_t)((j - 1) & 1));
                }
                uint32_t t = tiles + s * STAGE_BYTES;
                MBARRIER_EXPECT_TX(fb, STAGE_BYTES);
                bulk_copy_g2s(t,          Ah + ((size_t)c << 14), 16384, fb);
                bulk_copy_g2s(t + 16384,  Al + ((size_t)c << 14), 16384, fb);
                bulk_copy_g2s(t + 32768,  Wh + ((size_t)c << 14), 16384, fb);
                bulk_copy_g2s(t + 49152,  Wl + ((size_t)c << 14), 16384, fb);
            }
        }
        return;   // producer warp exits; no epilogue work
    }

    // ================= compute warps (0-7) =================
    const int a_row = wm * 64 + (lane & 15);
    const int a_kb  = (lane >> 4) * 16;
    const int b_row = wn * 32 + ((lane >> 4) << 3) + (lane & 7);
    const int b_kb  = ((lane >> 3) & 1) * 16;

    float acc[4][4][4];
#pragma unroll
    for (int i = 0; i < 4; i++)
#pragma unroll
        for (int j = 0; j < 4; j++)
#pragma unroll
            for (int q = 0; q < 4; q++) acc[i][j][q] = 0.0f;

    for (int c = 0; c < NKC_SPLIT; c++) {
        int s = c % NSTG;
        uint32_t fb   = sbase + 16 * s;
        uint32_t cons = sbase + 48 + 16 * s;
        mbar_wait_parity(fb, (uint32_t)((c / NSTG) & 1));

        uint32_t t  = tiles + s * STAGE_BYTES;
        uint32_t tAh = t, tAl = t + 16384, tBh = t + 32768, tBl = t + 49152;

#pragma unroll
        for (int kk = 0; kk < 4; kk++) {
            uint32_t afh[4][4], afl[4][4];
            uint32_t bfh[2][4], bfl[2][4];
#pragma unroll
            for (int mb = 0; mb < 4; mb++) {
                uint32_t off = SWZ((uint32_t)((a_row + mb * 16) * 128 + kk * 32 + a_kb));
                ldmatrix_x4(afh[mb][0], afh[mb][1], afh[mb][2], afh[mb][3], tAh + off);
                ldmatrix_x4(afl[mb][0], afl[mb][1], afl[mb][2], afl[mb][3], tAl + off);
            }
#pragma unroll
            for (int np = 0; np < 2; np++) {
                uint32_t off = SWZ((uint32_t)((b_row + np * 16) * 128 + kk * 32 + b_kb));
                ldmatrix_x4(bfh[np][0], bfh[np][1], bfh[np][2], bfh[np][3], tBh + off);
                ldmatrix_x4(bfl[np][0], bfl[np][1], bfl[np][2], bfl[np][3], tBl + off);
            }
            // After the last ldmatrix of this stage, this warp is done reading
            // the stage's smem — signal the producer (refill overlaps MMAs).
            if (kk == 3 && lane == 0) MBARRIER_ARRIVE(cons);

#pragma unroll
            for (int mb = 0; mb < 4; mb++) {
#pragma unroll
                for (int nb = 0; nb < 4; nb++) {
                    int np = nb >> 1, h = (nb & 1) * 2;
                    mma_16816(acc[mb][nb], afh[mb], bfh[np][h], bfh[np][h + 1]);
                    mma_16816(acc[mb][nb], afh[mb], bfl[np][h], bfl[np][h + 1]);
                    mma_16816(acc[mb][nb], afl[mb], bfh[np][h], bfh[np][h + 1]);
                }
            }
        }
    }

    // ---- epilogue: store fp32 partials (each warp owns its region) ----
    float* part = g_part[ks];
    const int col_base = bn * 128 + wn * 32;
    const int row_base = bm * 128 + wm * 64 + (lane >> 2);
    const int csub = (lane & 3) * 2;

#pragma unroll
    for (int mb = 0; mb < 4; mb++) {
#pragma unroll
        for (int half = 0; half < 2; half++) {
            int row = row_base + mb * 16 + half * 8;
            if (row < ntok) {
                float* op = part + (size_t)row * DOUT + col_base + csub;
#pragma unroll
                for (int nb = 0; nb < 4; nb++) {
                    float2 w;
                    w.x = acc[mb][nb][half * 2 + 0];
                    w.y = acc[mb][nb][half * 2 + 1];
                    *(float2*)(op + nb * 8) = w;
                }
            }
        }
    }
}

// ---------------------------------------------------------------------------
// Kernel 3: reduce split-K partials + bias -> out
// ---------------------------------------------------------------------------
__global__ void reduce_kernel(const float* __restrict__ bias,
                              float* __restrict__ out, int total4) {
    int idx = blockIdx.x * blockDim.x + threadIdx.x;
    if (idx >= total4) return;
    float4 p0 = ((const float4*)g_part[0])[idx];
    float4 p1 = ((const float4*)g_part[1])[idx];
    float4 p2 = ((const float4*)g_part[2])[idx];
    int col = (idx * 4) % DOUT;
    float4 b = *(const float4*)(bias + col);
    float4 w;
    w.x = p0.x + p1.x + p2.x + b.x;
    w.y = p0.y + p1.y + p2.y + b.y;
    w.z = p0.z + p1.z + p2.z + b.z;
    w.w = p0.w + p1.w + p2.w + b.w;
    ((float4*)out)[idx] = w;
}

// ---------------------------------------------------------------------------
// Launch — inputs: x, coef, scale_base, scale_sp, bias
// ---------------------------------------------------------------------------
extern "C" void kernel_launch(void* const* d_in, const int* in_sizes, int n_in,
                              void* d_out, int out_size) {
    const float* x          = (const float*)d_in[0];
    const float* coef       = (const float*)d_in[1];
    const float* scale_base = (const float*)d_in[2];
    const float* scale_sp   = (const float*)d_in[3];
    const float* bias       = (const float*)d_in[4];
    float* out = (float*)d_out;

    int ntok = in_sizes[0] / DIN;
    if (ntok > MAX_NTOK) ntok = MAX_NTOK;
    int mtiles = (ntok + 127) / 128;

    // 1) fused prep: pack W tiles + build A tiles (concurrent, low-reg, div-free)
    {
        int nblk_build = ntok * 3;   // one block per (token, 256-feature segment)
        prep_kernel<<<NBLK_PACK + nblk_build, 256>>>(x, coef, scale_base, scale_sp, ntok);
    }
    // 2) tensor-core GEMM (mma.sync bf16x3, split-K x3, warp-specialized pipe)
    {
        const int smem_req = NSTG * 65536 + 2048;
        cudaFuncSetAttribute(gemm_kernel, cudaFuncAttributeMaxDynamicSharedMemorySize, smem_req);
        dim3 grid(NT, mtiles, NSPLIT);
        gemm_kernel<<<grid, 288, smem_req>>>(ntok);
    }
    // 3) reduce partials + bias
    {
        int total4 = ntok * DOUT / 4;
        reduce_kernel<<<(total4 + 255) / 256, 256>>>(bias, out, total4);
    }
}